// round 11
// baseline (speedup 1.0000x reference)
#include <cuda_runtime.h>
#include <cstdint>

#define BATCH  8192
#define DCONT  1024
#define VCAT   10000
#define VEC    2500          // float4s per categorical row
#define FULL   0xffffffffu
#define NWARP  4
#define NCHUNK 20            // chunks of 128 float4 (2 KB) per row
#define CHUNKB 2048
#define NSTAGE 4

__device__ __forceinline__ void cp16(unsigned saddr, const void* gaddr) {
    asm volatile("cp.async.cg.shared.global [%0], [%1], 16;\n"
                 :: "r"(saddr), "l"(gaddr));
}
__device__ __forceinline__ void cp_commit() {
    asm volatile("cp.async.commit_group;\n" ::: "memory");
}
template <int N>
__device__ __forceinline__ void cp_wait() {
    asm volatile("cp.async.wait_group %0;\n" :: "n"(N) : "memory");
}

// Copy one chunk (vec indices [chunk*128, chunk*128+128)) into a ring stage.
// Layout: segment j, lane l -> stage byte (j*32+l)*16. Guarded for the tail.
__device__ __forceinline__ void issue_chunk(const uint4* __restrict__ xr,
                                            int chunk, unsigned sbase, int lane) {
    int v = chunk * 128 + lane;
    unsigned sa = sbase + (unsigned)lane * 16u;
    #pragma unroll
    for (int j = 0; j < 4; j++)
        if (v + j * 32 < VEC) cp16(sa + j * 512u, xr + v + j * 32);
}

// Scan one staged chunk; rare warp-uniform walk gathers W_cat rows
// (broadcast c-quarter load, add predicated on g==0).
__device__ __forceinline__ void process_chunk(const char* stage, int chunk,
                                              const float4* __restrict__ Wcat4,
                                              float4& acc, int& cnt,
                                              int lane, int g, int c, bool tail) {
    const uint4* sp = reinterpret_cast<const uint4*>(stage) + lane;
    uint4 v0 = sp[0];
    uint4 v1 = sp[32];
    uint4 v2 = sp[64];
    uint4 v3 = sp[96];
    if (tail) {                                 // chunk 19: mask stale slots
        const uint4 z = make_uint4(0u, 0u, 0u, 0u);
        if (lane >= 4) v2 = z;
        v3 = z;
    }
    unsigned m =
          (v0.x ? 0x0001u : 0u) | (v0.y ? 0x0002u : 0u)
        | (v0.z ? 0x0004u : 0u) | (v0.w ? 0x0008u : 0u)
        | (v1.x ? 0x0010u : 0u) | (v1.y ? 0x0020u : 0u)
        | (v1.z ? 0x0040u : 0u) | (v1.w ? 0x0080u : 0u)
        | (v2.x ? 0x0100u : 0u) | (v2.y ? 0x0200u : 0u)
        | (v2.z ? 0x0400u : 0u) | (v2.w ? 0x0800u : 0u)
        | (v3.x ? 0x1000u : 0u) | (v3.y ? 0x2000u : 0u)
        | (v3.z ? 0x4000u : 0u) | (v3.w ? 0x8000u : 0u);
    cnt += __popc(m);
    unsigned bal = __ballot_sync(FULL, m != 0u);
    while (bal) {                               // ~0.64 sources per chunk
        int src = __ffs(bal) - 1;
        bal &= bal - 1;
        unsigned sm = __shfl_sync(FULL, m, src); // warp-uniform from here on
        int vb = chunk * 128 + src;
        #pragma unroll
        for (int j = 0; j < 4; j++) {
            unsigned mj = (sm >> (4 * j)) & 0xfu;
            if (mj) {
                int colb = (vb + j * 32) * 4;
                #pragma unroll
                for (int k = 0; k < 4; k++) {
                    if (mj & (1u << k)) {
                        float4 w = __ldg(Wcat4 + (size_t)(colb + k) * 4 + c);
                        if (g == 0) { acc.x += w.x; acc.y += w.y;
                                      acc.z += w.z; acc.w += w.w; }
                    }
                }
            }
        }
    }
}

__global__ void __launch_bounds__(128, 7)
spfl_kernel(const float* __restrict__ xcont,
            const float* __restrict__ xcat,
            const float* __restrict__ Wc,
            const float* __restrict__ Wcat,
            const float* __restrict__ bias,
            float* __restrict__ out) {
    __shared__ __align__(16) char buf[NWARP][NSTAGE][CHUNKB];   // 32 KB

    const int wid  = threadIdx.x >> 5;
    const int lane = threadIdx.x & 31;
    const int g = lane >> 2;
    const int c = lane & 3;
    const int wg = blockIdx.x * NWARP + wid;
    const int row0 = wg * 2;                   // exact grid: no bounds check

    const uint4*  __restrict__ xr0   = reinterpret_cast<const uint4*>(xcat) + (size_t)row0 * VEC;
    const uint4*  __restrict__ xr1   = xr0 + VEC;
    const float4* __restrict__ Wcat4 = reinterpret_cast<const float4*>(Wcat);
    const float4* __restrict__ Wc4   = reinterpret_cast<const float4*>(Wc);

    char* wbuf = &buf[wid][0][0];
    unsigned sb = (unsigned)__cvta_generic_to_shared(wbuf);

    // Slot s: row = s&1, chunk = s>>1, stage = s&3. Prologue fills slots 0..2.
    issue_chunk(xr0, 0, sb + 0 * CHUNKB, lane); cp_commit();
    issue_chunk(xr1, 0, sb + 1 * CHUNKB, lane); cp_commit();
    issue_chunk(xr0, 1, sb + 2 * CHUNKB, lane); cp_commit();

    float4 acc0 = make_float4(0.f, 0.f, 0.f, 0.f);
    float4 acc1 = make_float4(0.f, 0.f, 0.f, 0.f);
    int cnt0 = 0, cnt1 = 0;

    #pragma unroll 1
    for (int ch = 0; ch < NCHUNK; ch++) {
        const bool tail = (ch == NCHUNK - 1);
        // slot 2ch (row0, chunk ch); keep fetch queue full before processing
        cp_wait<2>();
        if (ch + 1 < NCHUNK)
            issue_chunk(xr1, ch + 1, sb + (unsigned)(((2*ch + 3) & 3) * CHUNKB), lane);
        cp_commit();                            // unconditional: keeps group math exact
        process_chunk(wbuf + ((2*ch) & 3) * CHUNKB, ch, Wcat4, acc0, cnt0, lane, g, c, tail);
        // slot 2ch+1 (row1, chunk ch)
        cp_wait<2>();
        if (ch + 2 < NCHUNK)
            issue_chunk(xr0, ch + 2, sb + (unsigned)(((2*ch + 4) & 3) * CHUNKB), lane);
        cp_commit();
        process_chunk(wbuf + ((2*ch + 1) & 3) * CHUNKB, ch, Wcat4, acc1, cnt1, lane, g, c, tail);
    }

    // ---- continuous branch: proven c/g layout (512B-contiguous W loads) ----
    const float* __restrict__ xc0 = xcont + (size_t)row0 * DCONT;
    const float* __restrict__ xc1 = xc0 + DCONT;
    #pragma unroll 1
    for (int jb = 0; jb < DCONT; jb += 32) {
        float x0 = __ldg(xc0 + jb + lane);
        float x1 = __ldg(xc1 + jb + lane);
        #pragma unroll
        for (int s = 0; s < 4; s++) {
            int jl = s * 8 + g;
            float4 w = __ldg(Wc4 + (size_t)(jb + jl) * 4 + c);
            float a0 = __shfl_sync(FULL, x0, jl);
            float a1 = __shfl_sync(FULL, x1, jl);
            acc0.x += a0 * w.x; acc0.y += a0 * w.y; acc0.z += a0 * w.z; acc0.w += a0 * w.w;
            acc1.x += a1 * w.x; acc1.y += a1 * w.y; acc1.z += a1 * w.z; acc1.w += a1 * w.w;
        }
    }

    // ---- reduce acc over g (offsets 4,8,16); counts over all lanes ----
    #pragma unroll
    for (int off = 4; off <= 16; off <<= 1) {
        acc0.x += __shfl_xor_sync(FULL, acc0.x, off);
        acc0.y += __shfl_xor_sync(FULL, acc0.y, off);
        acc0.z += __shfl_xor_sync(FULL, acc0.z, off);
        acc0.w += __shfl_xor_sync(FULL, acc0.w, off);
        acc1.x += __shfl_xor_sync(FULL, acc1.x, off);
        acc1.y += __shfl_xor_sync(FULL, acc1.y, off);
        acc1.z += __shfl_xor_sync(FULL, acc1.z, off);
        acc1.w += __shfl_xor_sync(FULL, acc1.w, off);
    }
    #pragma unroll
    for (int off = 1; off <= 16; off <<= 1) {
        cnt0 += __shfl_xor_sync(FULL, cnt0, off);
        cnt1 += __shfl_xor_sync(FULL, cnt1, off);
    }

    if (lane < 4) {   // g == 0, quarter c == lane
        float4 b4 = __ldg(reinterpret_cast<const float4*>(bias) + lane);
        float f0 = (float)(DCONT + cnt0);
        float f1 = (float)(DCONT + cnt1);
        float4 o0, o1;
        o0.x = acc0.x + f0 * b4.x; o0.y = acc0.y + f0 * b4.y;
        o0.z = acc0.z + f0 * b4.z; o0.w = acc0.w + f0 * b4.w;
        o1.x = acc1.x + f1 * b4.x; o1.y = acc1.y + f1 * b4.y;
        o1.z = acc1.z + f1 * b4.z; o1.w = acc1.w + f1 * b4.w;
        reinterpret_cast<float4*>(out)[(size_t)row0 * 4 + lane]       = o0;
        reinterpret_cast<float4*>(out)[(size_t)(row0 + 1) * 4 + lane] = o1;
    }
}

extern "C" void kernel_launch(void* const* d_in, const int* in_sizes, int n_in,
                              void* d_out, int out_size) {
    const float* xcont = (const float*)d_in[0];   // [8192, 1024]
    const float* xcat  = (const float*)d_in[1];   // [8192, 10000]
    const float* Wc    = (const float*)d_in[2];   // [1024, 16]
    const float* Wcat  = (const float*)d_in[3];   // [10000, 16]
    const float* bias  = (const float*)d_in[4];   // [16]
    float* out = (float*)d_out;                   // [8192, 16]

    // 2 rows per warp, 4 warps per block -> 1024 blocks (single wave)
    dim3 grid(BATCH / (2 * NWARP));
    dim3 block(32 * NWARP);
    spfl_kernel<<<grid, block>>>(xcont, xcat, Wc, Wcat, bias, out);
}

// round 12
// speedup vs baseline: 1.4247x; 1.4247x over previous
#include <cuda_runtime.h>
#include <cstdint>

#define BATCH 8192
#define DCONT 1024
#define VCAT  10000
#define VEC   2500           // float4s per categorical row
#define FULL  0xffffffffu
#define NSTEP 80             // chunks of 32 vectors (78.125 -> 79 real, 80 padded)

__device__ __forceinline__ float u2f(unsigned u) { return __uint_as_float(u); }

// Walk one ballot'd source vector: broadcast its 4 components, gather W_cat
// rows (64B broadcast load, add predicated on g==0). Warp-uniform control.
__device__ __forceinline__ void walk(unsigned bal, uint4 v, int chunk,
                                     const float4* __restrict__ Wcat4,
                                     float4& acc, int g, int c4) {
    while (bal) {
        int src = __ffs(bal) - 1;
        bal &= bal - 1;
        unsigned sx = __shfl_sync(FULL, v.x, src);
        unsigned sy = __shfl_sync(FULL, v.y, src);
        unsigned sz = __shfl_sync(FULL, v.z, src);
        unsigned sw = __shfl_sync(FULL, v.w, src);
        int col = (chunk * 32 + src) * 4;
        if (sx) { float4 w = __ldg(Wcat4 + (size_t)(col + 0) * 4 + c4);
            if (g == 0) { acc.x += w.x; acc.y += w.y; acc.z += w.z; acc.w += w.w; } }
        if (sy) { float4 w = __ldg(Wcat4 + (size_t)(col + 1) * 4 + c4);
            if (g == 0) { acc.x += w.x; acc.y += w.y; acc.z += w.z; acc.w += w.w; } }
        if (sz) { float4 w = __ldg(Wcat4 + (size_t)(col + 2) * 4 + c4);
            if (g == 0) { acc.x += w.x; acc.y += w.y; acc.z += w.z; acc.w += w.w; } }
        if (sw) { float4 w = __ldg(Wcat4 + (size_t)(col + 3) * 4 + c4);
            if (g == 0) { acc.x += w.x; acc.y += w.y; acc.z += w.z; acc.w += w.w; } }
    }
}

__global__ void __launch_bounds__(128, 7)
spfl_kernel(const float* __restrict__ xcont,
            const float* __restrict__ xcat,
            const float* __restrict__ Wc,
            const float* __restrict__ Wcat,
            const float* __restrict__ bias,
            float* __restrict__ out) {
    const int warp = (blockIdx.x * blockDim.x + threadIdx.x) >> 5;
    const int lane = threadIdx.x & 31;
    const int g  = lane >> 2;
    const int c4 = lane & 3;
    const int row0 = warp * 2;                 // exact grid, no bounds check

    const uint4*  __restrict__ xr0   = reinterpret_cast<const uint4*>(xcat) + (size_t)row0 * VEC;
    const uint4*  __restrict__ xr1   = xr0 + VEC;
    const float4* __restrict__ Wcat4 = reinterpret_cast<const float4*>(Wcat);
    const float4* __restrict__ Wc4   = reinterpret_cast<const float4*>(Wc);

    float4 acc0 = make_float4(0.f, 0.f, 0.f, 0.f);
    float4 acc1 = make_float4(0.f, 0.f, 0.f, 0.f);
    float fcnt0 = 0.f, fcnt1 = 0.f;

    const uint4 z = make_uint4(0u, 0u, 0u, 0u);
    uint4 A[4], B[4];                          // 4-stage ring: A=row0, B=row1

    // Prologue: stages 0..2 hold chunks 0..2 (all fully in range: 95 < 2500)
    #pragma unroll
    for (int s = 0; s < 3; s++) {
        int idx = s * 32 + lane;
        A[s] = __ldg(xr0 + idx);
        B[s] = __ldg(xr1 + idx);
    }
    A[3] = z; B[3] = z;

    // Main: distance-3 prefetch; 3 chunks (1.5 KB/row) in flight per warp
    #pragma unroll 4
    for (int ch = 0; ch < NSTEP; ch++) {
        const int pf = ch + 3;                 // chunk to prefetch
        const int st = pf & 3;
        {
            int idx = pf * 32 + lane;
            uint4 na = z, nb = z;
            if (pf < NSTEP && idx < VEC) {     // tail chunk 78: lanes 0-3 only
                na = __ldg(xr0 + idx);
                nb = __ldg(xr1 + idx);
            }
            A[st] = na; B[st] = nb;
        }
        const int cur = ch & 3;
        uint4 v = A[cur];
        uint4 w = B[cur];
        // counts on the FMA pipe: mask entries are exact 0.0f / 1.0f
        fcnt0 += (u2f(v.x) + u2f(v.y)) + (u2f(v.z) + u2f(v.w));
        fcnt1 += (u2f(w.x) + u2f(w.y)) + (u2f(w.z) + u2f(w.w));
        unsigned bal0 = __ballot_sync(FULL, (v.x | v.y | v.z | v.w) != 0u);
        unsigned bal1 = __ballot_sync(FULL, (w.x | w.y | w.z | w.w) != 0u);
        if (bal0) walk(bal0, v, ch, Wcat4, acc0, g, c4);
        if (bal1) walk(bal1, w, ch, Wcat4, acc1, g, c4);
    }

    // ---- continuous branch: proven c/g layout (512B-contiguous W loads) ----
    const float* __restrict__ xc0 = xcont + (size_t)row0 * DCONT;
    const float* __restrict__ xc1 = xc0 + DCONT;
    #pragma unroll 1
    for (int jb = 0; jb < DCONT; jb += 32) {
        float x0 = __ldg(xc0 + jb + lane);
        float x1 = __ldg(xc1 + jb + lane);
        #pragma unroll
        for (int s = 0; s < 4; s++) {
            int jl = s * 8 + g;
            float4 w = __ldg(Wc4 + (size_t)(jb + jl) * 4 + c4);
            float a0 = __shfl_sync(FULL, x0, jl);
            float a1 = __shfl_sync(FULL, x1, jl);
            acc0.x += a0 * w.x; acc0.y += a0 * w.y; acc0.z += a0 * w.z; acc0.w += a0 * w.w;
            acc1.x += a1 * w.x; acc1.y += a1 * w.y; acc1.z += a1 * w.z; acc1.w += a1 * w.w;
        }
    }

    // ---- reduce acc over g (offsets 4,8,16); counts over all lanes ----
    #pragma unroll
    for (int off = 4; off <= 16; off <<= 1) {
        acc0.x += __shfl_xor_sync(FULL, acc0.x, off);
        acc0.y += __shfl_xor_sync(FULL, acc0.y, off);
        acc0.z += __shfl_xor_sync(FULL, acc0.z, off);
        acc0.w += __shfl_xor_sync(FULL, acc0.w, off);
        acc1.x += __shfl_xor_sync(FULL, acc1.x, off);
        acc1.y += __shfl_xor_sync(FULL, acc1.y, off);
        acc1.z += __shfl_xor_sync(FULL, acc1.z, off);
        acc1.w += __shfl_xor_sync(FULL, acc1.w, off);
    }
    #pragma unroll
    for (int off = 1; off <= 16; off <<= 1) {
        fcnt0 += __shfl_xor_sync(FULL, fcnt0, off);
        fcnt1 += __shfl_xor_sync(FULL, fcnt1, off);
    }

    if (lane < 4) {   // g == 0, quarter c4 == lane
        float4 b4 = __ldg(reinterpret_cast<const float4*>(bias) + lane);
        float f0 = (float)DCONT + fcnt0;
        float f1 = (float)DCONT + fcnt1;
        float4 o0, o1;
        o0.x = acc0.x + f0 * b4.x; o0.y = acc0.y + f0 * b4.y;
        o0.z = acc0.z + f0 * b4.z; o0.w = acc0.w + f0 * b4.w;
        o1.x = acc1.x + f1 * b4.x; o1.y = acc1.y + f1 * b4.y;
        o1.z = acc1.z + f1 * b4.z; o1.w = acc1.w + f1 * b4.w;
        reinterpret_cast<float4*>(out)[(size_t)row0 * 4 + lane]       = o0;
        reinterpret_cast<float4*>(out)[(size_t)(row0 + 1) * 4 + lane] = o1;
    }
}

extern "C" void kernel_launch(void* const* d_in, const int* in_sizes, int n_in,
                              void* d_out, int out_size) {
    const float* xcont = (const float*)d_in[0];   // [8192, 1024]
    const float* xcat  = (const float*)d_in[1];   // [8192, 10000]
    const float* Wc    = (const float*)d_in[2];   // [1024, 16]
    const float* Wcat  = (const float*)d_in[3];   // [10000, 16]
    const float* bias  = (const float*)d_in[4];   // [16]
    float* out = (float*)d_out;                   // [8192, 16]

    // 2 rows per warp, 4 warps per block -> 1024 blocks (single wave)
    dim3 grid(BATCH / 8);
    dim3 block(128);
    spfl_kernel<<<grid, block>>>(xcont, xcat, Wc, Wcat, bias, out);
}

// round 13
// speedup vs baseline: 1.5055x; 1.0567x over previous
#include <cuda_runtime.h>
#include <cstdint>

#define BATCH  8192
#define DCONT  1024
#define VCAT   10000
#define VEC    2500          // float4s per categorical row
#define FULL   0xffffffffu
#define NWARP  4
#define NCHUNK 20            // chunks of 128 vectors per row
#define CAP    640           // 20 ballots * 32 bits = hard max entries per row

// Build 16-bit nonzero mask for 4 float4 vectors (values are exact 0.0/1.0)
__device__ __forceinline__ unsigned mask16(uint4 v0, uint4 v1, uint4 v2, uint4 v3) {
    return (v0.x ? 0x0001u : 0u) | (v0.y ? 0x0002u : 0u)
         | (v0.z ? 0x0004u : 0u) | (v0.w ? 0x0008u : 0u)
         | (v1.x ? 0x0010u : 0u) | (v1.y ? 0x0020u : 0u)
         | (v1.z ? 0x0040u : 0u) | (v1.w ? 0x0080u : 0u)
         | (v2.x ? 0x0100u : 0u) | (v2.y ? 0x0200u : 0u)
         | (v2.z ? 0x0400u : 0u) | (v2.w ? 0x0800u : 0u)
         | (v3.x ? 0x1000u : 0u) | (v3.y ? 0x2000u : 0u)
         | (v3.z ? 0x4000u : 0u) | (v3.w ? 0x8000u : 0u);
}

// Phase 2: lanes gather recorded W_cat rows in parallel, butterfly-reduce,
// return this lane's output quarter (lanes 0-3; zero elsewhere).
__device__ __forceinline__ float4 gather_reduce(const unsigned* __restrict__ l,
                                                int nE,
                                                const float4* __restrict__ Wcat4,
                                                int lane) {
    float a[16];
    #pragma unroll
    for (int k = 0; k < 16; k++) a[k] = 0.f;

    #pragma unroll 1
    for (int e = lane; e < nE; e += 32) {
        unsigned ent = l[e];
        int idx = (int)(ent >> 16);            // vec index of segment 0
        unsigned m = ent & 0xffffu;
        #pragma unroll
        for (int k = 0; k < 4; k++) {          // 4 vectors per entry
            unsigned mk = (m >> (4 * k)) & 0xfu;
            if (mk) {
                int colb = (idx + 32 * k) * 4;
                #pragma unroll
                for (int j = 0; j < 4; j++) {
                    if (mk & (1u << j)) {
                        const float4* w = Wcat4 + (size_t)(colb + j) * 4;
                        float4 t0 = __ldg(w + 0), t1 = __ldg(w + 1);
                        float4 t2 = __ldg(w + 2), t3 = __ldg(w + 3);
                        a[0]+=t0.x;  a[1]+=t0.y;  a[2]+=t0.z;  a[3]+=t0.w;
                        a[4]+=t1.x;  a[5]+=t1.y;  a[6]+=t1.z;  a[7]+=t1.w;
                        a[8]+=t2.x;  a[9]+=t2.y;  a[10]+=t2.z; a[11]+=t2.w;
                        a[12]+=t3.x; a[13]+=t3.y; a[14]+=t3.z; a[15]+=t3.w;
                    }
                }
            }
        }
    }
    #pragma unroll
    for (int off = 16; off >= 1; off >>= 1) {
        #pragma unroll
        for (int k = 0; k < 16; k++) a[k] += __shfl_xor_sync(FULL, a[k], off);
    }
    float4 r = make_float4(0.f, 0.f, 0.f, 0.f);
    if      (lane == 0) r = make_float4(a[0],  a[1],  a[2],  a[3]);
    else if (lane == 1) r = make_float4(a[4],  a[5],  a[6],  a[7]);
    else if (lane == 2) r = make_float4(a[8],  a[9],  a[10], a[11]);
    else if (lane == 3) r = make_float4(a[12], a[13], a[14], a[15]);
    return r;
}

__global__ void __launch_bounds__(128, 7)
spfl_kernel(const float* __restrict__ xcont,
            const float* __restrict__ xcat,
            const float* __restrict__ Wc,
            const float* __restrict__ Wcat,
            const float* __restrict__ bias,
            float* __restrict__ out) {
    __shared__ unsigned lst[NWARP][2][CAP];    // 20 KB/block

    const int wid  = threadIdx.x >> 5;
    const int lane = threadIdx.x & 31;
    const int warp = blockIdx.x * NWARP + wid;
    const int row0 = warp * 2;                 // exact grid: no bounds check
    const unsigned lt = (1u << lane) - 1u;

    const uint4*  __restrict__ xr0   = reinterpret_cast<const uint4*>(xcat) + (size_t)row0 * VEC;
    const uint4*  __restrict__ xr1   = xr0 + VEC;
    const float4* __restrict__ Wcat4 = reinterpret_cast<const float4*>(Wcat);
    const float4* __restrict__ Wc4   = reinterpret_cast<const float4*>(Wc);

    // ========== Phase 1: pure prefetched stream; record nonzero groups ======
    int nE0 = 0, nE1 = 0, cnt0 = 0, cnt1 = 0;
    const uint4 z = make_uint4(0u, 0u, 0u, 0u);

    uint4 a0 = __ldcs(xr0 + lane),      a1 = __ldcs(xr0 + lane + 32);
    uint4 a2 = __ldcs(xr0 + lane + 64), a3 = __ldcs(xr0 + lane + 96);
    uint4 b0 = __ldcs(xr1 + lane),      b1 = __ldcs(xr1 + lane + 32);
    uint4 b2 = __ldcs(xr1 + lane + 64), b3 = __ldcs(xr1 + lane + 96);

    #pragma unroll 1
    for (int c = 0; c < NCHUNK; c++) {
        uint4 n0 = z, n1 = z, n2 = z, n3 = z;
        uint4 p0 = z, p1 = z, p2 = z, p3 = z;
        if (c < 18) {                          // full prefetch of chunk c+1
            const uint4* q0 = xr0 + (c + 1) * 128 + lane;
            const uint4* q1 = xr1 + (c + 1) * 128 + lane;
            n0 = __ldcs(q0); n1 = __ldcs(q0 + 32); n2 = __ldcs(q0 + 64); n3 = __ldcs(q0 + 96);
            p0 = __ldcs(q1); p1 = __ldcs(q1 + 32); p2 = __ldcs(q1 + 64); p3 = __ldcs(q1 + 96);
        } else if (c == 18) {                  // partial tail chunk 19
            int b = 19 * 128 + lane;
            n0 = __ldcs(xr0 + b); p0 = __ldcs(xr1 + b);              // always < 2500
            n1 = __ldcs(xr0 + b + 32); p1 = __ldcs(xr1 + b + 32);    // always < 2500
            if (b + 64 < VEC) { n2 = __ldcs(xr0 + b + 64); p2 = __ldcs(xr1 + b + 64); }
        }

        // row0: mask, count, ballot, append (no gathers, no shuffles)
        unsigned m0 = mask16(a0, a1, a2, a3);
        cnt0 += __popc(m0);
        unsigned bal0 = __ballot_sync(FULL, m0 != 0u);
        if (m0) lst[wid][0][nE0 + __popc(bal0 & lt)] =
                    ((unsigned)(c * 128 + lane) << 16) | m0;
        nE0 += __popc(bal0);

        // row1
        unsigned m1 = mask16(b0, b1, b2, b3);
        cnt1 += __popc(m1);
        unsigned bal1 = __ballot_sync(FULL, m1 != 0u);
        if (m1) lst[wid][1][nE1 + __popc(bal1 & lt)] =
                    ((unsigned)(c * 128 + lane) << 16) | m1;
        nE1 += __popc(bal1);

        a0 = n0; a1 = n1; a2 = n2; a3 = n3;
        b0 = p0; b1 = p1; b2 = p2; b3 = p3;
    }

    __syncwarp();

    // ========== Phase 2: parallel gather + reduce per row ===================
    float4 acc0 = gather_reduce(&lst[wid][0][0], nE0, Wcat4, lane);
    float4 acc1 = gather_reduce(&lst[wid][1][0], nE1, Wcat4, lane);

    // ========== Continuous branch: proven c/g layout ========================
    const int g  = lane >> 2;
    const int c4 = lane & 3;
    const float* __restrict__ xc0 = xcont + (size_t)row0 * DCONT;
    const float* __restrict__ xc1 = xc0 + DCONT;
    #pragma unroll 1
    for (int jb = 0; jb < DCONT; jb += 32) {
        float x0 = __ldg(xc0 + jb + lane);
        float x1 = __ldg(xc1 + jb + lane);
        #pragma unroll
        for (int s = 0; s < 4; s++) {
            int jl = s * 8 + g;
            float4 w = __ldg(Wc4 + (size_t)(jb + jl) * 4 + c4);
            float v0 = __shfl_sync(FULL, x0, jl);
            float v1 = __shfl_sync(FULL, x1, jl);
            acc0.x += v0 * w.x; acc0.y += v0 * w.y; acc0.z += v0 * w.z; acc0.w += v0 * w.w;
            acc1.x += v1 * w.x; acc1.y += v1 * w.y; acc1.z += v1 * w.z; acc1.w += v1 * w.w;
        }
    }

    // ---- reduce cont partials over g (cat quarters ride in g==0 lanes) ----
    #pragma unroll
    for (int off = 4; off <= 16; off <<= 1) {
        acc0.x += __shfl_xor_sync(FULL, acc0.x, off);
        acc0.y += __shfl_xor_sync(FULL, acc0.y, off);
        acc0.z += __shfl_xor_sync(FULL, acc0.z, off);
        acc0.w += __shfl_xor_sync(FULL, acc0.w, off);
        acc1.x += __shfl_xor_sync(FULL, acc1.x, off);
        acc1.y += __shfl_xor_sync(FULL, acc1.y, off);
        acc1.z += __shfl_xor_sync(FULL, acc1.z, off);
        acc1.w += __shfl_xor_sync(FULL, acc1.w, off);
    }
    #pragma unroll
    for (int off = 1; off <= 16; off <<= 1) {
        cnt0 += __shfl_xor_sync(FULL, cnt0, off);
        cnt1 += __shfl_xor_sync(FULL, cnt1, off);
    }

    if (lane < 4) {   // g==0, quarter c4 == lane
        float4 b4 = __ldg(reinterpret_cast<const float4*>(bias) + lane);
        float f0 = (float)(DCONT + cnt0);
        float f1 = (float)(DCONT + cnt1);
        float4 o0, o1;
        o0.x = acc0.x + f0 * b4.x; o0.y = acc0.y + f0 * b4.y;
        o0.z = acc0.z + f0 * b4.z; o0.w = acc0.w + f0 * b4.w;
        o1.x = acc1.x + f1 * b4.x; o1.y = acc1.y + f1 * b4.y;
        o1.z = acc1.z + f1 * b4.z; o1.w = acc1.w + f1 * b4.w;
        reinterpret_cast<float4*>(out)[(size_t)row0 * 4 + lane]       = o0;
        reinterpret_cast<float4*>(out)[(size_t)(row0 + 1) * 4 + lane] = o1;
    }
}

extern "C" void kernel_launch(void* const* d_in, const int* in_sizes, int n_in,
                              void* d_out, int out_size) {
    const float* xcont = (const float*)d_in[0];   // [8192, 1024]
    const float* xcat  = (const float*)d_in[1];   // [8192, 10000]
    const float* Wc    = (const float*)d_in[2];   // [1024, 16]
    const float* Wcat  = (const float*)d_in[3];   // [10000, 16]
    const float* bias  = (const float*)d_in[4];   // [16]
    float* out = (float*)d_out;                   // [8192, 16]

    // 2 rows per warp, 4 warps per block -> 1024 blocks (single wave)
    dim3 grid(BATCH / (2 * NWARP));
    dim3 block(32 * NWARP);
    spfl_kernel<<<grid, block>>>(xcont, xcat, Wc, Wcat, bias, out);
}